// round 15
// baseline (speedup 1.0000x reference)
#include <cuda_runtime.h>
#include <cstdint>

typedef unsigned long long U64;

__device__ __forceinline__ U64 pack2(float x) {
    U64 r; asm("mov.b64 %0, {%1, %1};" : "=l"(r) : "f"(x)); return r;
}
__device__ __forceinline__ void fma2(U64 &acc, U64 a, U64 b) {
    asm("fma.rn.f32x2 %0, %1, %2, %0;" : "+l"(acc) : "l"(a), "l"(b));
}
__device__ __forceinline__ float hsum2(U64 a) {
    float lo, hi; asm("mov.b64 {%0,%1}, %2;" : "=f"(lo), "=f"(hi) : "l"(a));
    return lo + hi;
}
__device__ __forceinline__ float sigmoid_f(float x) {
    return 1.f / (1.f + __expf(-x));
}
__device__ __forceinline__ float tanh_exp(float x) {
    float e = __expf(2.f * x);
    return 1.f - __fdividef(2.f, e + 1.f);
}

#define B_    256
#define T_    1024
#define F_    128
#define UU    64
#define NPRE  320   // P cols: [Emu_x(64) | Elv_x(64) | Wg_x(192)]
#define NW1   512

__device__ float g_Wc[F_ * NPRE];
__device__ float g_W1p[UU * NW1];          // k-pair + thread-role permuted
__device__ float g_P[B_ * T_ * NPRE];

// ---------------------------------------------------------------------------
// Prep A: g_Wc = W_in (128x128) @ [Emu[:128] | Elv[:128] | Wg[:128]]
// ---------------------------------------------------------------------------
__global__ void k_prep_wc(const float* __restrict__ Win,
                          const float* __restrict__ Emu,
                          const float* __restrict__ Elv,
                          const float* __restrict__ Wg) {
    int r = blockIdx.x;
    int c = threadIdx.x;
    float s = 0.f;
    if (c < 64) {
        for (int k = 0; k < F_; k++) s += Win[r*F_ + k] * Emu[k*64 + c];
    } else if (c < 128) {
        int j = c - 64;
        for (int k = 0; k < F_; k++) s += Win[r*F_ + k] * Elv[k*64 + j];
    } else {
        int j = c - 128;
        for (int k = 0; k < F_; k++) s += Win[r*F_ + k] * Wg[k*192 + j];
    }
    g_Wc[r*NPRE + c] = s;
}

// ---------------------------------------------------------------------------
// Prep B: role-permuted, k-pair-packed W1 (unchanged layout)
// ---------------------------------------------------------------------------
__global__ void k_prep_w1(const float* __restrict__ S,
                          const float* __restrict__ Pmu,
                          const float* __restrict__ Plv,
                          const float* __restrict__ Emu,
                          const float* __restrict__ Elv,
                          const float* __restrict__ R) {
    int r = blockIdx.x;      // k index 0..63
    int c = threadIdx.x;     // original col 0..511
    float v;
    if (c < 64) {
        v = S[r*64 + c];
    } else {
        int j = c - 64;
        float s = 0.f;
        if (j < 64)       { for (int k = 0; k < 64; k++) s += S[r*64+k] * Pmu[k*64 + j]; }
        else if (j < 128) { int jj = j-64;  for (int k = 0; k < 64; k++) s += S[r*64+k] * Plv[k*64 + jj]; }
        else if (j < 192) { int jj = j-128; for (int k = 0; k < 64; k++) s += S[r*64+k] * Emu[(128+k)*64 + jj]; }
        else if (j < 256) { int jj = j-192; for (int k = 0; k < 64; k++) s += S[r*64+k] * Elv[(128+k)*64 + jj]; }
        else              { int jj = j-256; for (int k = 0; k < 64; k++) s += S[r*64+k] * R[k*192 + jj]; }
        v = s;
    }
    int slot;
    if      (c < 64)  slot = 2*(128 + (c >> 1)) + (c & 1);
    else if (c < 128) slot = 2*(64 + (c - 64));
    else if (c < 192) slot = 2*(64 + (c - 128)) + 1;
    else if (c < 256) slot = 2*(c - 192);
    else if (c < 320) slot = 2*(c - 256) + 1;
    else              slot = 2*(160 + ((c - 320) >> 1)) + ((c - 320) & 1);
    g_W1p[(r >> 1) * 1024 + 2*slot + (r & 1)] = v;
}

// ---------------------------------------------------------------------------
// GEMM v4-persistent (round-11 measured-best, verbatim)
// ---------------------------------------------------------------------------
#define GBM 128
#define GBN 64
#define SA_STRIDE 133
#define GEMM_SMEM_BYTES ((128*SA_STRIDE + 128*GBN) * 4)
#define NTILES (2048 * 5)
#define GEMM_GRID 296

__global__ void __launch_bounds__(128, 2) k_gemm_p(const float* __restrict__ x) {
    extern __shared__ float sm[];
    float* sA = sm;
    float* sB = sm + 128 * SA_STRIDE;
    int tid = threadIdx.x;
    int cg = tid & 7, rg = tid >> 3;
    int c0 = cg << 3, r0 = rg << 3;

    for (int tile = blockIdx.x; tile < NTILES; tile += GEMM_GRID) {
        int nq = tile / 5;
        int nb = (tile - nq * 5) * GBN;
        long mb = (long)nq * GBM;

        for (int i = tid; i < 128 * 32; i += 128) {
            int r = i >> 5, c4 = (i & 31) << 2;
            float4 v = *(const float4*)(x + (mb + r) * F_ + c4);
            float* d = sA + r * SA_STRIDE + c4;
            d[0] = v.x; d[1] = v.y; d[2] = v.z; d[3] = v.w;
        }
        for (int i = tid; i < 128 * 16; i += 128) {
            int k = i >> 4, c4 = (i & 15) << 2;
            *(float4*)(sB + k * GBN + c4) = *(const float4*)(g_Wc + k * NPRE + nb + c4);
        }
        __syncthreads();

        U64 acc[8][4];
#pragma unroll
        for (int i = 0; i < 8; i++)
#pragma unroll
            for (int j = 0; j < 4; j++) acc[i][j] = 0ull;

#pragma unroll 4
        for (int k = 0; k < 128; k++) {
            ulonglong2 b01 = *(const ulonglong2*)(sB + k*GBN + c0);
            ulonglong2 b23 = *(const ulonglong2*)(sB + k*GBN + c0 + 4);
#pragma unroll
            for (int i = 0; i < 8; i++) {
                U64 p = pack2(sA[(r0+i)*SA_STRIDE + k]);
                fma2(acc[i][0], p, b01.x); fma2(acc[i][1], p, b01.y);
                fma2(acc[i][2], p, b23.x); fma2(acc[i][3], p, b23.y);
            }
        }

#pragma unroll
        for (int i = 0; i < 8; i++) {
            float* dst = g_P + (mb + r0 + i) * NPRE + nb + c0;
            ulonglong2 v0; v0.x = acc[i][0]; v0.y = acc[i][1];
            *(ulonglong2*)dst = v0;
            ulonglong2 v1; v1.x = acc[i][2]; v1.y = acc[i][3];
            *(ulonglong2*)(dst + 4) = v1;
        }
        __syncthreads();
    }
}

// ---------------------------------------------------------------------------
// Recurrent kernel v7: ONE batch row per CTA, 256 CTAs, occupancy 2.
// Same 3-phase structure as v4, but per-CTA state halved:
//   W1 regs: 2 cols/thread = 64 regs. M1: 2 cols x 1 row (2 U64 acc).
//   M2: 192 threads, full-K single column each (W2 k-pair packed in smem).
// Two co-resident CTAs per SM overlap each other's latency/barrier tails.
// ---------------------------------------------------------------------------
#define OFF7_W2P 0             // [32 kp][384] : [kp][2c+par] = W2[2kp+par][c]
#define OFF7_B0  12288         // [192]
#define OFF7_B1  12480         // [192]
#define OFF7_H   12672         // [64]
#define OFF7_ZF  12736         // [64] plain z  (U64-pair readable)
#define OFF7_HP  12800         // [64]
#define OFF7_MH  12864         // [192]
#define OFF7_G   13056         // [192]
#define RNN_SMEM_FLOATS 13248
#define RNN_SMEM_BYTES  (RNN_SMEM_FLOATS * 4)

__global__ void __launch_bounds__(256, 2) k_rnn(const float* __restrict__ gbias,
                                                const float* __restrict__ gruk,
                                                float* __restrict__ out) {
    extern __shared__ float sm[];
    float* sW2p = sm + OFF7_W2P;
    float* sB0  = sm + OFF7_B0;
    float* sB1  = sm + OFF7_B1;
    float* sH   = sm + OFF7_H;
    float* sZf  = sm + OFF7_ZF;
    float* sHP  = sm + OFF7_HP;
    float* sMH  = sm + OFF7_MH;
    float* sG   = sm + OFF7_G;

    int tid = threadIdx.x;
    int row = blockIdx.x;

    // --- W2 (gru_kernel rows 128..191) k-pair packed ---
    for (int i = tid; i < 64 * 192; i += 256) {
        int k = i / 192, c = i - k * 192;
        sW2p[(k >> 1) * 384 + 2*c + (k & 1)] = gruk[(128 + k) * 192 + c];
    }
    if (tid < 96)
        *(float4*)(sB0 + tid*4) = *(const float4*)(gbias + tid*4);
    if (tid < 64) sH[tid] = 0.f;

    // --- W1 regs: thread t owns permuted slots 2t, 2t+1 (2 cols), k-pair ---
    U64 w1a[32], w1b[32];
#pragma unroll
    for (int i = 0; i < 32; i++) {
        ulonglong2 v = *(const ulonglong2*)(g_W1p + i * 1024 + (tid << 2));
        w1a[i] = v.x; w1b[i] = v.y;
    }

    const int SEQ = B_ * T_ * UU;
    const float* Prow = g_P + (long)row * T_ * NPRE;
    int u = tid - 64;                       // gate/elt2 unit (valid tid 64..127)

    // current-step P registers
    float cz0 = 0.f, cz1 = 0.f, cg0 = 0.f, cg1 = 0.f, cg2 = 0.f;
    if (tid < 64) {
        cz0 = Prow[tid];  cz1 = Prow[64 + tid];
    } else if (tid < 128) {
        cg0 = Prow[128 + u]; cg1 = Prow[192 + u]; cg2 = Prow[256 + u];
    }

    // bias hoist for elt2 threads
    float bz0 = 0.f, bz1 = 0.f, bz2 = 0.f, br0 = 0.f, br1 = 0.f, br2 = 0.f;
    __syncthreads();
    if (tid >= 64 && tid < 128) {
        bz0 = sB0[u]; bz1 = sB0[64 + u]; bz2 = sB0[128 + u];
        br0 = sB1[u]; br1 = sB1[64 + u]; br2 = sB1[128 + u];
    }

#pragma unroll 1
    for (int t = 0; t < T_; t++) {
        // prefetch next step's P (clamped last iter)
        int tn = (t + 1 < T_) ? (t + 1) : t;
        long offn = (long)tn * NPRE;
        float nz0 = 0.f, nz1 = 0.f, ng0 = 0.f, ng1 = 0.f, ng2 = 0.f;
        if (tid < 64) {
            nz0 = Prow[offn + tid];  nz1 = Prow[offn + 64 + tid];
        } else if (tid < 128) {
            ng0 = Prow[offn + 128 + u];
            ng1 = Prow[offn + 192 + u];
            ng2 = Prow[offn + 256 + u];
        }

        // ---- M1: this thread's 2 cols, single row, K-SIMD
        const ulonglong2* h2 = (const ulonglong2*)sH;
        U64 a0 = 0ull, a1 = 0ull;
#pragma unroll
        for (int i = 0; i < 16; i++) {
            ulonglong2 hv = h2[i];
            fma2(a0, hv.x, w1a[2*i]);   fma2(a1, hv.x, w1b[2*i]);
            fma2(a0, hv.y, w1a[2*i+1]); fma2(a1, hv.y, w1b[2*i+1]);
        }
        float y0 = hsum2(a0), y1 = hsum2(a1);

        // ---- role epilogue
        if (tid < 64) {
            float qmu = y0 + cz0, qlv = y1 + cz1;
            float z = 0.5f * __expf(qlv) + qmu;
            sZf[tid] = z;
            int base = (row * T_ + t) * UU + tid;
            out[base]         = z;
            out[base + SEQ]   = qmu;
            out[base + 3*SEQ] = qlv;
        } else if (tid < 128) {
            int base = (row * T_ + t) * UU + u;
            out[base + 2*SEQ] = y0;     // pmu
            out[base + 4*SEQ] = y1;     // plv
        } else if (tid < 160) {
            int j = tid - 128;
            *(float2*)(sHP + 2*j) = make_float2(y0, y1);
        } else {
            int j = tid - 160;
            *(float2*)(sMH + 2*j) = make_float2(y0, y1);
        }
        __syncthreads();

        // ---- M2: column tid, full K (32 kp), z broadcast as U64 pairs
        if (tid < 192) {
            U64 g = 0ull;
            const float* wp = sW2p + 2*tid;
            const U64* zp = (const U64*)sZf;
#pragma unroll
            for (int kp = 0; kp < 32; kp++)
                fma2(g, zp[kp], *(const U64*)(wp + kp * 384));
            sG[tid] = hsum2(g);
        }
        __syncthreads();

        // ---- elt2: threads 64..127, unit u
        if (tid >= 64 && tid < 128) {
            float hp  = sHP[u];
            float mhz = sMH[u]        + br0;
            float mhr = sMH[64 + u]   + br1;
            float mhh = sMH[128 + u]  + br2;
            float mxz = cg0 + sG[u]        + bz0;
            float mxr = cg1 + sG[64 + u]   + bz1;
            float mxh = cg2 + sG[128 + u]  + bz2;
            float zt = sigmoid_f(mxz + mhz);
            float rt = sigmoid_f(mxr + mhr);
            float hh = tanh_exp(mxh + rt * mhh);
            sH[u] = zt * hp + (1.f - zt) * hh;
        }
        __syncthreads();

        cz0 = nz0; cz1 = nz1;
        cg0 = ng0; cg1 = ng1; cg2 = ng2;
    }
}

// ---------------------------------------------------------------------------
extern "C" void kernel_launch(void* const* d_in, const int* in_sizes, int n_in,
                              void* d_out, int out_size) {
    const float* x   = (const float*)d_in[0];
    const float* Win = (const float*)d_in[1];
    const float* S   = (const float*)d_in[2];
    const float* Emu = (const float*)d_in[3];
    const float* Elv = (const float*)d_in[4];
    const float* Pmu = (const float*)d_in[5];
    const float* Plv = (const float*)d_in[6];
    const float* Wg  = (const float*)d_in[7];
    const float* R   = (const float*)d_in[8];
    const float* gb  = (const float*)d_in[9];

    cudaFuncSetAttribute(k_gemm_p, cudaFuncAttributeMaxDynamicSharedMemorySize, GEMM_SMEM_BYTES);
    cudaFuncSetAttribute(k_rnn,    cudaFuncAttributeMaxDynamicSharedMemorySize, RNN_SMEM_BYTES);

    k_prep_wc<<<128, 320>>>(Win, Emu, Elv, Wg);
    k_prep_w1<<<64, 512>>>(S, Pmu, Plv, Emu, Elv, R);

    k_gemm_p<<<GEMM_GRID, 128, GEMM_SMEM_BYTES>>>(x);

    k_rnn<<<256, 256, RNN_SMEM_BYTES>>>(gb, Wg, (float*)d_out);
}

// round 16
// speedup vs baseline: 2.0542x; 2.0542x over previous
#include <cuda_runtime.h>
#include <cstdint>

typedef unsigned long long U64;

__device__ __forceinline__ U64 pack2(float x) {
    U64 r; asm("mov.b64 %0, {%1, %1};" : "=l"(r) : "f"(x)); return r;
}
__device__ __forceinline__ void fma2(U64 &acc, U64 a, U64 b) {
    asm("fma.rn.f32x2 %0, %1, %2, %0;" : "+l"(acc) : "l"(a), "l"(b));
}
__device__ __forceinline__ float hsum2(U64 a) {
    float lo, hi; asm("mov.b64 {%0,%1}, %2;" : "=f"(lo), "=f"(hi) : "l"(a));
    return lo + hi;
}
__device__ __forceinline__ float sigmoid_f(float x) {
    return 1.f / (1.f + __expf(-x));
}
__device__ __forceinline__ float tanh_exp(float x) {
    float e = __expf(2.f * x);
    return 1.f - __fdividef(2.f, e + 1.f);
}

#define B_    256
#define T_    1024
#define F_    128
#define UU    64
#define NPRE  320   // P cols: [Emu_x(64) | Elv_x(64) | Wg_x(192)]
#define NW1   512

__device__ float g_Wc[F_ * NPRE];
__device__ float g_W1p[UU * NW1];          // k-pair + thread-role permuted
__device__ float g_P[B_ * T_ * NPRE];

// ---------------------------------------------------------------------------
// Merged prep: blocks 0..127 compute g_Wc rows (round-13 k_prep_wc),
// blocks 128..191 compute g_W1p rows (round-13 k_prep_w1). One launch.
// ---------------------------------------------------------------------------
__global__ void k_prep(const float* __restrict__ Win,
                       const float* __restrict__ Emu,
                       const float* __restrict__ Elv,
                       const float* __restrict__ Wg,
                       const float* __restrict__ S,
                       const float* __restrict__ Pmu,
                       const float* __restrict__ Plv,
                       const float* __restrict__ R) {
    if (blockIdx.x < 128) {
        // --- Wc role: r = blockIdx.x (k 0..127), c = tid (n 0..319) ---
        int r = blockIdx.x;
        int c = threadIdx.x;
        if (c >= 320) return;
        float s = 0.f;
        if (c < 64) {
            for (int k = 0; k < F_; k++) s += Win[r*F_ + k] * Emu[k*64 + c];
        } else if (c < 128) {
            int j = c - 64;
            for (int k = 0; k < F_; k++) s += Win[r*F_ + k] * Elv[k*64 + j];
        } else {
            int j = c - 128;
            for (int k = 0; k < F_; k++) s += Win[r*F_ + k] * Wg[k*192 + j];
        }
        g_Wc[r*NPRE + c] = s;
    } else {
        // --- W1 role: r = blockIdx.x-128 (k 0..63), c = tid (col 0..511) ---
        int r = blockIdx.x - 128;
        int c = threadIdx.x;
        float v;
        if (c < 64) {
            v = S[r*64 + c];
        } else {
            int j = c - 64;
            float s = 0.f;
            if (j < 64)       { for (int k = 0; k < 64; k++) s += S[r*64+k] * Pmu[k*64 + j]; }
            else if (j < 128) { int jj = j-64;  for (int k = 0; k < 64; k++) s += S[r*64+k] * Plv[k*64 + jj]; }
            else if (j < 192) { int jj = j-128; for (int k = 0; k < 64; k++) s += S[r*64+k] * Emu[(128+k)*64 + jj]; }
            else if (j < 256) { int jj = j-192; for (int k = 0; k < 64; k++) s += S[r*64+k] * Elv[(128+k)*64 + jj]; }
            else              { int jj = j-256; for (int k = 0; k < 64; k++) s += S[r*64+k] * R[k*192 + jj]; }
            v = s;
        }
        int slot;
        if      (c < 64)  slot = 2*(128 + (c >> 1)) + (c & 1);
        else if (c < 128) slot = 2*(64 + (c - 64));
        else if (c < 192) slot = 2*(64 + (c - 128)) + 1;
        else if (c < 256) slot = 2*(c - 192);
        else if (c < 320) slot = 2*(c - 256) + 1;
        else              slot = 2*(160 + ((c - 320) >> 1)) + ((c - 320) & 1);
        g_W1p[(r >> 1) * 1024 + 2*slot + (r & 1)] = v;
    }
}

// ---------------------------------------------------------------------------
// GEMM v4-persistent (round-11/13 measured-best, verbatim)
// ---------------------------------------------------------------------------
#define GBM 128
#define GBN 64
#define SA_STRIDE 133
#define GEMM_SMEM_BYTES ((128*SA_STRIDE + 128*GBN) * 4)
#define NTILES (2048 * 5)
#define GEMM_GRID 296

__global__ void __launch_bounds__(128, 2) k_gemm_p(const float* __restrict__ x) {
    extern __shared__ float sm[];
    float* sA = sm;
    float* sB = sm + 128 * SA_STRIDE;
    int tid = threadIdx.x;
    int cg = tid & 7, rg = tid >> 3;
    int c0 = cg << 3, r0 = rg << 3;

    for (int tile = blockIdx.x; tile < NTILES; tile += GEMM_GRID) {
        int nq = tile / 5;
        int nb = (tile - nq * 5) * GBN;
        long mb = (long)nq * GBM;

        for (int i = tid; i < 128 * 32; i += 128) {
            int r = i >> 5, c4 = (i & 31) << 2;
            float4 v = *(const float4*)(x + (mb + r) * F_ + c4);
            float* d = sA + r * SA_STRIDE + c4;
            d[0] = v.x; d[1] = v.y; d[2] = v.z; d[3] = v.w;
        }
        for (int i = tid; i < 128 * 16; i += 128) {
            int k = i >> 4, c4 = (i & 15) << 2;
            *(float4*)(sB + k * GBN + c4) = *(const float4*)(g_Wc + k * NPRE + nb + c4);
        }
        __syncthreads();

        U64 acc[8][4];
#pragma unroll
        for (int i = 0; i < 8; i++)
#pragma unroll
            for (int j = 0; j < 4; j++) acc[i][j] = 0ull;

#pragma unroll 4
        for (int k = 0; k < 128; k++) {
            ulonglong2 b01 = *(const ulonglong2*)(sB + k*GBN + c0);
            ulonglong2 b23 = *(const ulonglong2*)(sB + k*GBN + c0 + 4);
#pragma unroll
            for (int i = 0; i < 8; i++) {
                U64 p = pack2(sA[(r0+i)*SA_STRIDE + k]);
                fma2(acc[i][0], p, b01.x); fma2(acc[i][1], p, b01.y);
                fma2(acc[i][2], p, b23.x); fma2(acc[i][3], p, b23.y);
            }
        }

#pragma unroll
        for (int i = 0; i < 8; i++) {
            float* dst = g_P + (mb + r0 + i) * NPRE + nb + c0;
            ulonglong2 v0; v0.x = acc[i][0]; v0.y = acc[i][1];
            *(ulonglong2*)dst = v0;
            ulonglong2 v1; v1.x = acc[i][2]; v1.y = acc[i][3];
            *(ulonglong2*)(dst + 4) = v1;
        }
        __syncthreads();
    }
}

// ---------------------------------------------------------------------------
// Recurrent kernel v4.1 (round-13 measured-best, byte-identical: 1146 us)
// ---------------------------------------------------------------------------
#define OFF_W2  0
#define OFF_B0  12288
#define OFF_B1  12480
#define OFF_HP  12672
#define OFF_MH  12800
#define OFF_G   13184
#define OFF_H   13952
#define OFF_Z2  14080
#define RNN_SMEM_FLOATS 14336
#define RNN_SMEM_BYTES  (RNN_SMEM_FLOATS * 4)

__global__ void __launch_bounds__(256, 1) k_rnn(const float* __restrict__ gbias,
                                                const float* __restrict__ gruk,
                                                float* __restrict__ out) {
    extern __shared__ float sm[];
    float* sW2 = sm + OFF_W2;
    float* sB0 = sm + OFF_B0;
    float* sB1 = sm + OFF_B1;
    float* sHP = sm + OFF_HP;
    float* sMH = sm + OFF_MH;
    float* sG  = sm + OFF_G;
    float* sH  = sm + OFF_H;
    U64*   sZ2 = (U64*)(sm + OFF_Z2);

    int tid = threadIdx.x;
    int b0  = blockIdx.x * 2;

    for (int i = tid; i < (64*192)/4; i += 256)
        *(float4*)(sW2 + i*4) = *(const float4*)(gruk + 128*192 + i*4);
    if (tid < 96)
        *(float4*)(sB0 + tid*4) = *(const float4*)(gbias + tid*4);
    if (tid < 128) sH[tid] = 0.f;

    U64 w1a[32], w1b[32];
#pragma unroll
    for (int i = 0; i < 32; i++) {
        ulonglong2 v = *(const ulonglong2*)(g_W1p + i * 1024 + (tid << 2));
        w1a[i] = v.x; w1b[i] = v.y;
    }

    int re = tid >> 6, ue = tid & 63;
    int hf = (tid < 96) ? 0 : 1;
    int j2 = (tid < 96) ? tid : (tid - 96);
    int kb = hf << 5;

    const int SEQ = B_ * T_ * UU;
    const float* PZ0 = g_P + (long)(b0)     * T_ * NPRE + tid;
    const float* PZ1 = g_P + (long)(b0 + 1) * T_ * NPRE + tid;
    const float* PG  = g_P + (long)(b0 + re)* T_ * NPRE + 128 + ue;

    float cz0=0,cz1=0,cz2=0,cz3=0, cg0=0,cg1=0,cg2=0;
    if (tid < 64) {
        cz0 = PZ0[0];  cz1 = PZ0[64];
        cz2 = PZ1[0];  cz3 = PZ1[64];
    }
    if (tid < 128) {
        cg0 = PG[0];   cg1 = PG[64];  cg2 = PG[128];
    }
    __syncthreads();

    float bz0 = 0.f, bz1 = 0.f, bz2 = 0.f, br0 = 0.f, br1 = 0.f, br2 = 0.f;
    if (tid < 128) {
        bz0 = sB0[ue]; bz1 = sB0[64 + ue]; bz2 = sB0[128 + ue];
        br0 = sB1[ue]; br1 = sB1[64 + ue]; br2 = sB1[128 + ue];
    }

#pragma unroll 1
    for (int t = 0; t < T_; t++) {
        int tn = (t + 1 < T_) ? (t + 1) : t;
        long offn = (long)tn * NPRE;
        float nz0=0,nz1=0,nz2=0,nz3=0, ng0=0,ng1=0,ng2=0;
        if (tid < 64) {
            nz0 = PZ0[offn];      nz1 = PZ0[offn + 64];
            nz2 = PZ1[offn];      nz3 = PZ1[offn + 64];
        }
        if (tid < 128) {
            ng0 = PG[offn];  ng1 = PG[offn + 64];  ng2 = PG[offn + 128];
        }

        const ulonglong2* h0 = (const ulonglong2*)(sH);
        const ulonglong2* h1 = (const ulonglong2*)(sH + 64);
        U64 a00 = 0ull, a01 = 0ull, a10 = 0ull, a11 = 0ull;
#pragma unroll
        for (int i = 0; i < 16; i++) {
            ulonglong2 ha = h0[i];
            ulonglong2 hb = h1[i];
            fma2(a00, ha.x, w1a[2*i]);   fma2(a01, ha.x, w1b[2*i]);
            fma2(a10, hb.x, w1a[2*i]);   fma2(a11, hb.x, w1b[2*i]);
            fma2(a00, ha.y, w1a[2*i+1]); fma2(a01, ha.y, w1b[2*i+1]);
            fma2(a10, hb.y, w1a[2*i+1]); fma2(a11, hb.y, w1b[2*i+1]);
        }
        float y00 = hsum2(a00), y01 = hsum2(a01);
        float y10 = hsum2(a10), y11 = hsum2(a11);

        if (tid < 64) {
            float qmu0 = y00 + cz0, qlv0 = y01 + cz1;
            float qmu1 = y10 + cz2, qlv1 = y11 + cz3;
            float z0 = 0.5f * __expf(qlv0) + qmu0;
            float z1 = 0.5f * __expf(qlv1) + qmu1;
            sZ2[tid]      = pack2(z0);
            sZ2[64 + tid] = pack2(z1);
            int base0 = (b0 * T_ + t) * UU + tid;
            int base1 = base0 + T_ * UU;
            out[base0]          = z0;
            out[base0 + SEQ]    = qmu0;
            out[base0 + 3*SEQ]  = qlv0;
            out[base1]          = z1;
            out[base1 + SEQ]    = qmu1;
            out[base1 + 3*SEQ]  = qlv1;
        } else if (tid < 128) {
            int u = tid - 64;
            int base0 = (b0 * T_ + t) * UU + u;
            int base1 = base0 + T_ * UU;
            out[base0 + 2*SEQ] = y00;
            out[base0 + 4*SEQ] = y01;
            out[base1 + 2*SEQ] = y10;
            out[base1 + 4*SEQ] = y11;
        } else if (tid < 160) {
            int j = tid - 128;
            *(float2*)(sHP + 2*j)       = make_float2(y00, y01);
            *(float2*)(sHP + 64 + 2*j)  = make_float2(y10, y11);
        } else {
            int j = tid - 160;
            *(float2*)(sMH + 2*j)        = make_float2(y00, y01);
            *(float2*)(sMH + 192 + 2*j)  = make_float2(y10, y11);
        }
        __syncthreads();

        if (tid < 192) {
            U64 g0 = 0ull, g1 = 0ull;
            const float* w2 = sW2 + (j2 << 1);
#pragma unroll
            for (int kk = 0; kk < 32; kk += 2) {
                int k = kb + kk;
                ulonglong2 z0 = *(const ulonglong2*)(sZ2 + k);
                ulonglong2 z1 = *(const ulonglong2*)(sZ2 + 64 + k);
                U64 wa = *(const U64*)(w2 + k * 192);
                U64 wb = *(const U64*)(w2 + (k+1) * 192);
                fma2(g0, z0.x, wa); fma2(g1, z1.x, wa);
                fma2(g0, z0.y, wb); fma2(g1, z1.y, wb);
            }
            *(U64*)(sG + ((hf << 1) + 0) * 192 + (j2 << 1)) = g0;
            *(U64*)(sG + ((hf << 1) + 1) * 192 + (j2 << 1)) = g1;
        }
        __syncthreads();

        if (tid < 128) {
            const float* Ga = sG + re * 192;
            const float* Gb = sG + (2 + re) * 192;
            float hp  = sHP[re * 64 + ue];
            float mhz = sMH[re * 192 + ue]        + br0;
            float mhr = sMH[re * 192 + 64 + ue]   + br1;
            float mhh = sMH[re * 192 + 128 + ue]  + br2;
            float mxz = cg0 + Ga[ue]        + Gb[ue]        + bz0;
            float mxr = cg1 + Ga[64 + ue]   + Gb[64 + ue]   + bz1;
            float mxh = cg2 + Ga[128 + ue]  + Gb[128 + ue]  + bz2;
            float zt = sigmoid_f(mxz + mhz);
            float rt = sigmoid_f(mxr + mhr);
            float hh = tanh_exp(mxh + rt * mhh);
            sH[re * 64 + ue] = zt * hp + (1.f - zt) * hh;
        }
        __syncthreads();

        cz0 = nz0; cz1 = nz1; cz2 = nz2; cz3 = nz3;
        cg0 = ng0; cg1 = ng1; cg2 = ng2;
    }
}

// ---------------------------------------------------------------------------
extern "C" void kernel_launch(void* const* d_in, const int* in_sizes, int n_in,
                              void* d_out, int out_size) {
    const float* x   = (const float*)d_in[0];
    const float* Win = (const float*)d_in[1];
    const float* S   = (const float*)d_in[2];
    const float* Emu = (const float*)d_in[3];
    const float* Elv = (const float*)d_in[4];
    const float* Pmu = (const float*)d_in[5];
    const float* Plv = (const float*)d_in[6];
    const float* Wg  = (const float*)d_in[7];
    const float* R   = (const float*)d_in[8];
    const float* gb  = (const float*)d_in[9];

    cudaFuncSetAttribute(k_gemm_p, cudaFuncAttributeMaxDynamicSharedMemorySize, GEMM_SMEM_BYTES);
    cudaFuncSetAttribute(k_rnn,    cudaFuncAttributeMaxDynamicSharedMemorySize, RNN_SMEM_BYTES);

    k_prep<<<192, 512>>>(Win, Emu, Elv, Wg, S, Pmu, Plv, R);

    k_gemm_p<<<GEMM_GRID, 128, GEMM_SMEM_BYTES>>>(x);

    k_rnn<<<128, 256, RNN_SMEM_BYTES>>>(gb, Wg, (float*)d_out);
}